// round 1
// baseline (speedup 1.0000x reference)
#include <cuda_runtime.h>
#include <math.h>

// ---------------------------------------------------------------------------
// KernelMixingLayer: out = (exp(-|W_rbf| * cdist(x,x)) @ x) @ W_out^T + b_out
// B = F = OUT = 4096
//
// Round 1: correct fp32 SIMT baseline.
//   k0: g_sq[i] = ||x_i||^2
//   k1 (MODE 0, NT): S = x @ x^T, fused epilogue -> g_gram
//   k2 (MODE 1, NN): g_mixed = g_gram @ x
//   k3 (MODE 2, NT): out = g_mixed @ W_out^T + b_out
// ---------------------------------------------------------------------------

#define NDIM 4096

// Scratch in __device__ globals (allocation inside kernel_launch is forbidden).
__device__ float g_sq[NDIM];
__device__ float g_gram[(size_t)NDIM * NDIM];
__device__ float g_mixed[(size_t)NDIM * NDIM];

// ---- k0: row squared norms -------------------------------------------------
__global__ void rownorm_kernel(const float* __restrict__ x) {
    const int row = blockIdx.x;
    const float4* xr = reinterpret_cast<const float4*>(x + (size_t)row * NDIM);
    float s = 0.f;
    for (int i = threadIdx.x; i < NDIM / 4; i += blockDim.x) {
        float4 v = xr[i];
        s += v.x * v.x + v.y * v.y + v.z * v.z + v.w * v.w;
    }
    __shared__ float red[256];
    red[threadIdx.x] = s;
    __syncthreads();
    for (int off = 128; off > 0; off >>= 1) {
        if (threadIdx.x < off) red[threadIdx.x] += red[threadIdx.x + off];
        __syncthreads();
    }
    if (threadIdx.x == 0) g_sq[row] = red[0];
}

// ---- tiled fp32 GEMM, 128x128x16 tile, 256 threads, 8x8 per thread ---------
// MODE 0: NT (B row-major [N,K]) + dist/exp epilogue, C = g_gram
// MODE 1: NN (B row-major [K,N]) plain,               C = g_mixed
// MODE 2: NT + bias epilogue,                          C = Cext (d_out)
constexpr int BM = 128, BN = 128, BK = 16, TM = 8, TN = 8;
constexpr int SPAD = BM + 4;   // 132 floats: keeps float4 smem stores 16B-aligned

template <int MODE>
__global__ void __launch_bounds__(256, 2)
gemm4096(const float* __restrict__ Aext,
         const float* __restrict__ Bext,
         const float* __restrict__ aux,     // MODE0: W_rbf, MODE2: b_out
         float* __restrict__ Cext)
{
    __shared__ float As[BK][SPAD];
    __shared__ float Bs[BK][SPAD];

    const float* A = (MODE == 1) ? g_gram : (MODE == 2) ? g_mixed : Aext;
    const float* B = Bext;

    const int bm  = blockIdx.y * BM;
    const int bn  = blockIdx.x * BN;
    const int tid = threadIdx.x;
    const int tm  = (tid >> 4) * TM;   // 0..120
    const int tn  = (tid & 15) * TN;   // 0..120

    float acc[TM][TN];
#pragma unroll
    for (int i = 0; i < TM; i++)
#pragma unroll
        for (int j = 0; j < TN; j++) acc[i][j] = 0.f;

    for (int kt = 0; kt < NDIM; kt += BK) {
        // --- load A tile [BM x BK], store transposed As[k][m]
#pragma unroll
        for (int l = 0; l < 2; l++) {
            int idx = tid + l * 256;                 // 0..511 (512 float4)
            int r = idx >> 2;                        // 0..127
            int c = (idx & 3) * 4;                   // 0,4,8,12
            float4 v = *reinterpret_cast<const float4*>(
                A + (size_t)(bm + r) * NDIM + kt + c);
            As[c + 0][r] = v.x;
            As[c + 1][r] = v.y;
            As[c + 2][r] = v.z;
            As[c + 3][r] = v.w;
        }
        // --- load B tile
        if (MODE == 1) {
            // NN: B is [K,N]; tile rows kt..kt+15, cols bn..bn+127
#pragma unroll
            for (int l = 0; l < 2; l++) {
                int idx = tid + l * 256;
                int kr = idx >> 5;                   // 0..15
                int c  = (idx & 31) * 4;             // 0..124
                *reinterpret_cast<float4*>(&Bs[kr][c]) =
                    *reinterpret_cast<const float4*>(
                        B + (size_t)(kt + kr) * NDIM + bn + c);
            }
        } else {
            // NT: B is [N,K]; tile rows bn..bn+127, cols kt..kt+15
#pragma unroll
            for (int l = 0; l < 2; l++) {
                int idx = tid + l * 256;
                int r = idx >> 2;
                int c = (idx & 3) * 4;
                float4 v = *reinterpret_cast<const float4*>(
                    B + (size_t)(bn + r) * NDIM + kt + c);
                Bs[c + 0][r] = v.x;
                Bs[c + 1][r] = v.y;
                Bs[c + 2][r] = v.z;
                Bs[c + 3][r] = v.w;
            }
        }
        __syncthreads();

#pragma unroll
        for (int k = 0; k < BK; k++) {
            float a[TM], b[TN];
#pragma unroll
            for (int i = 0; i < TM; i++) a[i] = As[k][tm + i];
#pragma unroll
            for (int j = 0; j < TN; j++) b[j] = Bs[k][tn + j];
#pragma unroll
            for (int i = 0; i < TM; i++)
#pragma unroll
                for (int j = 0; j < TN; j++)
                    acc[i][j] = fmaf(a[i], b[j], acc[i][j]);
        }
        __syncthreads();
    }

    // --- epilogue -----------------------------------------------------------
#pragma unroll
    for (int i = 0; i < TM; i++) {
        const int row = bm + tm + i;
        float* crow;
        if (MODE == 0)      crow = g_gram  + (size_t)row * NDIM;
        else if (MODE == 1) crow = g_mixed + (size_t)row * NDIM;
        else                crow = Cext    + (size_t)row * NDIM;

        if (MODE == 0) {
            const float sqi = g_sq[row];
            const float* wrow = aux + (size_t)row * NDIM;
#pragma unroll
            for (int j = 0; j < TN; j++) {
                const int col = bn + tn + j;
                float d2 = sqi + g_sq[col] - 2.f * acc[i][j];
                d2 = fmaxf(d2, 0.f);
                float d = sqrtf(d2);
                acc[i][j] = expf(-fabsf(wrow[col]) * d);
            }
        } else if (MODE == 2) {
#pragma unroll
            for (int j = 0; j < TN; j++)
                acc[i][j] += aux[bn + tn + j];
        }
#pragma unroll
        for (int j = 0; j < TN; j += 4) {
            float4 v = make_float4(acc[i][j], acc[i][j + 1],
                                   acc[i][j + 2], acc[i][j + 3]);
            *reinterpret_cast<float4*>(&crow[bn + tn + j]) = v;
        }
    }
}

// ---------------------------------------------------------------------------
extern "C" void kernel_launch(void* const* d_in, const int* in_sizes, int n_in,
                              void* d_out, int out_size)
{
    const float* x     = (const float*)d_in[0];   // [4096,4096]
    const float* W_rbf = (const float*)d_in[1];   // [4096,4096]
    const float* W_out = (const float*)d_in[2];   // [4096,4096]
    const float* b_out = (const float*)d_in[3];   // [4096]
    float* out = (float*)d_out;

    dim3 grid(NDIM / BN, NDIM / BM);   // 32 x 32
    dim3 block(256);

    rownorm_kernel<<<NDIM, 256>>>(x);
    gemm4096<0><<<grid, block>>>(x, x, W_rbf, nullptr);        // S -> gram
    gemm4096<1><<<grid, block>>>(nullptr, x, nullptr, nullptr); // gram @ x
    gemm4096<2><<<grid, block>>>(nullptr, W_out, b_out, out);   // @ W_out^T + b
}

// round 4
// speedup vs baseline: 7.2491x; 7.2491x over previous
#include <cuda_runtime.h>
#include <cuda_fp16.h>
#include <cstdint>
#include <math.h>

#define NDIM 4096

// ---------------- device scratch (no allocs allowed) ------------------------
__device__ float  g_sq[NDIM];
__device__ __half g_xh    [(size_t)NDIM * NDIM];   // x  fp16 [B,F]
__device__ __half g_xth   [(size_t)NDIM * NDIM];   // x^T fp16 [F,B]
__device__ __half g_wouth [(size_t)NDIM * NDIM];   // W_out fp16 [OUT,F]
__device__ __half g_gramh [(size_t)NDIM * NDIM];   // gram fp16
__device__ __half g_mixedh[(size_t)NDIM * NDIM];   // mixed fp16

// ---------------- helpers ---------------------------------------------------
__device__ __forceinline__ uint32_t smem_u32(const void* p) {
    uint32_t a;
    asm("{ .reg .u64 t; cvta.to.shared.u64 t, %1; cvt.u32.u64 %0, t; }"
        : "=r"(a) : "l"(p));
    return a;
}
__device__ __forceinline__ void cp16(uint32_t dst, const void* src) {
    asm volatile("cp.async.cg.shared.global [%0], [%1], 16;"
                 :: "r"(dst), "l"(src) : "memory");
}
__device__ __forceinline__ void cp_commit() {
    asm volatile("cp.async.commit_group;" ::: "memory");
}
__device__ __forceinline__ void cp_wait1() {
    asm volatile("cp.async.wait_group 1;" ::: "memory");
}
__device__ __forceinline__ uint32_t swz64(uint32_t off) {
    return off ^ ((off >> 3) & 0x30);          // 64B-row swizzle
}
__device__ __forceinline__ void ldsm4(uint32_t& r0, uint32_t& r1,
                                      uint32_t& r2, uint32_t& r3, uint32_t a) {
    asm volatile("ldmatrix.sync.aligned.m8n8.x4.shared.b16 {%0,%1,%2,%3}, [%4];"
                 : "=r"(r0), "=r"(r1), "=r"(r2), "=r"(r3) : "r"(a));
}
__device__ __forceinline__ void mma16816(float* c, const uint32_t* a,
                                         const uint32_t* b) {
    asm volatile(
        "mma.sync.aligned.m16n8k16.row.col.f32.f16.f16.f32 "
        "{%0,%1,%2,%3}, {%4,%5,%6,%7}, {%8,%9}, {%0,%1,%2,%3};"
        : "+f"(c[0]), "+f"(c[1]), "+f"(c[2]), "+f"(c[3])
        : "r"(a[0]), "r"(a[1]), "r"(a[2]), "r"(a[3]), "r"(b[0]), "r"(b[1]));
}

// ---------------- GEMM config ----------------------------------------------
constexpr int BM = 128, BN = 128, BK = 32;     // BK halves = 64 B rows
constexpr int NITER  = NDIM / BK;              // 128
constexpr int STAGE_BYTES = (BM + BN) * BK * 2;        // 16384
constexpr int B_OFF  = BM * BK * 2;                    // 8192

// MODE 0: S = x x^T + dist/exp -> g_gramh
// MODE 1: mixed = gram @ x (B = x^T)   -> g_mixedh
// MODE 2: out = mixed @ W_out^T + b    -> Cext (fp32)
template <int MODE>
__global__ void __launch_bounds__(256)
hmma_gemm(const float* __restrict__ aux, float* __restrict__ Cext)
{
    __shared__ __align__(1024) char smem[3 * STAGE_BYTES];   // 48 KB
    const uint32_t sb = smem_u32(smem);

    const int tid = threadIdx.x, wid = tid >> 5, lane = tid & 31;
    const int bm = blockIdx.y * BM, bn = blockIdx.x * BN;
    const int wm = (wid >> 2) * 64;      // 2 warps along M
    const int wn = (wid & 3) * 32;       // 4 warps along N

    const __half* Ag = (MODE == 0) ? g_xh : (MODE == 1) ? g_gramh : g_mixedh;
    const __half* Bg = (MODE == 0) ? g_xh : (MODE == 1) ? g_xth   : g_wouth;

    // per-thread cp.async source/dest (2 x 16B chunks each for A and B)
    const int ch0 = tid, ch1 = tid + 256;
    const int ra0 = ch0 >> 2, ca0 = ch0 & 3;
    const int ra1 = ch1 >> 2, ca1 = ch1 & 3;
    const __half* gA0 = Ag + (size_t)(bm + ra0) * NDIM + ca0 * 8;
    const __half* gA1 = Ag + (size_t)(bm + ra1) * NDIM + ca1 * 8;
    const __half* gB0 = Bg + (size_t)(bn + ra0) * NDIM + ca0 * 8;
    const __half* gB1 = Bg + (size_t)(bn + ra1) * NDIM + ca1 * 8;
    const uint32_t sA0 = swz64(ra0 * 64 + ca0 * 16);
    const uint32_t sA1 = swz64(ra1 * 64 + ca1 * 16);
    const uint32_t sB0 = swz64(ra0 * 64 + ca0 * 16);
    const uint32_t sB1 = swz64(ra1 * 64 + ca1 * 16);

    // ldmatrix lane offsets (bytes, pre-swizzle)
    const uint32_t aRB = (uint32_t)(wm + (lane & 15)) * 64 + (lane >> 4) * 16;
    const uint32_t bRB = (uint32_t)(wn + (lane & 7) + ((lane >> 4) << 3)) * 64 +
                         ((lane >> 3) & 1) * 16;

    float acc[4][4][4];
#pragma unroll
    for (int i = 0; i < 4; i++)
#pragma unroll
        for (int j = 0; j < 4; j++)
#pragma unroll
            for (int q = 0; q < 4; q++) acc[i][j][q] = 0.f;

    // prologue: tiles 0,1
#pragma unroll
    for (int t = 0; t < 2; t++) {
        const uint32_t base = sb + t * STAGE_BYTES;
        const int kt = t * BK;
        cp16(base + sA0, gA0 + kt);
        cp16(base + sA1, gA1 + kt);
        cp16(base + B_OFF + sB0, gB0 + kt);
        cp16(base + B_OFF + sB1, gB1 + kt);
        cp_commit();
    }

    for (int it = 0; it < NITER; ++it) {
        cp_wait1();
        __syncthreads();

        const int nt = it + 2;
        if (nt < NITER) {
            const uint32_t base = sb + (nt % 3) * STAGE_BYTES;
            const int kt = nt * BK;
            cp16(base + sA0, gA0 + kt);
            cp16(base + sA1, gA1 + kt);
            cp16(base + B_OFF + sB0, gB0 + kt);
            cp16(base + B_OFF + sB1, gB1 + kt);
        }
        cp_commit();

        const uint32_t abase = sb + (it % 3) * STAGE_BYTES;
        const uint32_t bbase = abase + B_OFF;

#pragma unroll
        for (int ks = 0; ks < 2; ks++) {
            uint32_t af[4][4], bf[4][2];
#pragma unroll
            for (int mf = 0; mf < 4; mf++)
                ldsm4(af[mf][0], af[mf][1], af[mf][2], af[mf][3],
                      abase + swz64(aRB + mf * 1024 + ks * 32));
#pragma unroll
            for (int nf2 = 0; nf2 < 2; nf2++) {
                uint32_t r0, r1, r2, r3;
                // B stored [N,K] (NT): NON-trans ldmatrix yields the correct
                // (k-pair, fixed n) mma B fragment. (.trans was the R3 bug.)
                ldsm4(r0, r1, r2, r3,
                      bbase + swz64(bRB + nf2 * 1024 + ks * 32));
                bf[2 * nf2][0] = r0; bf[2 * nf2][1] = r1;
                bf[2 * nf2 + 1][0] = r2; bf[2 * nf2 + 1][1] = r3;
            }
#pragma unroll
            for (int mf = 0; mf < 4; mf++)
#pragma unroll
                for (int nf = 0; nf < 4; nf++)
                    mma16816(acc[mf][nf], af[mf], bf[nf]);
        }
    }

    // ---------------- epilogue (register accumulators) ----------------------
    const int rb = bm + wm + (lane >> 2);
    const int cb = bn + wn + (lane & 3) * 2;

    if (MODE == 0) {
        float2 sqc[4];
#pragma unroll
        for (int nf = 0; nf < 4; nf++)
            sqc[nf] = *reinterpret_cast<const float2*>(&g_sq[cb + nf * 8]);
#pragma unroll
        for (int mf = 0; mf < 4; mf++)
#pragma unroll
            for (int rs = 0; rs < 2; rs++) {
                const int row = rb + mf * 16 + rs * 8;
                const float sqi = g_sq[row];
                const float* wr = aux + (size_t)row * NDIM;
                __half* orow = g_gramh + (size_t)row * NDIM;
#pragma unroll
                for (int nf = 0; nf < 4; nf++) {
                    const int col = cb + nf * 8;
                    float2 w2 = *reinterpret_cast<const float2*>(&wr[col]);
                    float s0 = acc[mf][nf][rs * 2 + 0];
                    float s1 = acc[mf][nf][rs * 2 + 1];
                    float d0 = sqrtf(fmaxf(sqi + sqc[nf].x - 2.f * s0, 0.f));
                    float d1 = sqrtf(fmaxf(sqi + sqc[nf].y - 2.f * s1, 0.f));
                    __half2 h = __floats2half2_rn(__expf(-fabsf(w2.x) * d0),
                                                  __expf(-fabsf(w2.y) * d1));
                    *reinterpret_cast<__half2*>(&orow[col]) = h;
                }
            }
    } else if (MODE == 1) {
#pragma unroll
        for (int mf = 0; mf < 4; mf++)
#pragma unroll
            for (int rs = 0; rs < 2; rs++) {
                const int row = rb + mf * 16 + rs * 8;
                __half* orow = g_mixedh + (size_t)row * NDIM;
#pragma unroll
                for (int nf = 0; nf < 4; nf++) {
                    __half2 h = __floats2half2_rn(acc[mf][nf][rs * 2 + 0],
                                                  acc[mf][nf][rs * 2 + 1]);
                    *reinterpret_cast<__half2*>(&orow[cb + nf * 8]) = h;
                }
            }
    } else {
        float2 bias2[4];
#pragma unroll
        for (int nf = 0; nf < 4; nf++)
            bias2[nf] = *reinterpret_cast<const float2*>(&aux[cb + nf * 8]);
#pragma unroll
        for (int mf = 0; mf < 4; mf++)
#pragma unroll
            for (int rs = 0; rs < 2; rs++) {
                const int row = rb + mf * 16 + rs * 8;
                float* orow = Cext + (size_t)row * NDIM;
#pragma unroll
                for (int nf = 0; nf < 4; nf++) {
                    float2 v;
                    v.x = acc[mf][nf][rs * 2 + 0] + bias2[nf].x;
                    v.y = acc[mf][nf][rs * 2 + 1] + bias2[nf].y;
                    *reinterpret_cast<float2*>(&orow[cb + nf * 8]) = v;
                }
            }
    }
}

// ---------------- prep kernels ---------------------------------------------
__global__ void rownorm_kernel(const float* __restrict__ x) {
    const int row = blockIdx.x;
    const float4* xr = reinterpret_cast<const float4*>(x + (size_t)row * NDIM);
    float s = 0.f;
    for (int i = threadIdx.x; i < NDIM / 4; i += blockDim.x) {
        float4 v = xr[i];
        s += v.x * v.x + v.y * v.y + v.z * v.z + v.w * v.w;
    }
    __shared__ float red[256];
    red[threadIdx.x] = s;
    __syncthreads();
    for (int off = 128; off > 0; off >>= 1) {
        if (threadIdx.x < off) red[threadIdx.x] += red[threadIdx.x + off];
        __syncthreads();
    }
    if (threadIdx.x == 0) g_sq[row] = red[0];
}

template <int DST>   // 0 -> g_xh, 1 -> g_wouth
__global__ void conv_half_kernel(const float* __restrict__ src) {
    size_t i = ((size_t)blockIdx.x * blockDim.x + threadIdx.x) * 8;
    const float4* s = reinterpret_cast<const float4*>(src + i);
    float4 a = s[0], b = s[1];
    __half2 h0 = __floats2half2_rn(a.x, a.y);
    __half2 h1 = __floats2half2_rn(a.z, a.w);
    __half2 h2 = __floats2half2_rn(b.x, b.y);
    __half2 h3 = __floats2half2_rn(b.z, b.w);
    uint4 o;
    o.x = *reinterpret_cast<uint32_t*>(&h0);
    o.y = *reinterpret_cast<uint32_t*>(&h1);
    o.z = *reinterpret_cast<uint32_t*>(&h2);
    o.w = *reinterpret_cast<uint32_t*>(&h3);
    __half* dst = DST == 0 ? g_xh : g_wouth;
    *reinterpret_cast<uint4*>(dst + i) = o;
}

__global__ void transp_kernel(const float* __restrict__ src) {
    __shared__ float t[32][33];
    const int bx = blockIdx.x * 32, by = blockIdx.y * 32;
    const int tx = threadIdx.x, ty = threadIdx.y;   // (32, 8)
#pragma unroll
    for (int j = 0; j < 32; j += 8)
        t[ty + j][tx] = src[(size_t)(by + ty + j) * NDIM + bx + tx];
    __syncthreads();
#pragma unroll
    for (int j = 0; j < 32; j += 8)
        g_xth[(size_t)(bx + ty + j) * NDIM + by + tx] = __float2half(t[tx][ty + j]);
}

// ---------------------------------------------------------------------------
extern "C" void kernel_launch(void* const* d_in, const int* in_sizes, int n_in,
                              void* d_out, int out_size)
{
    const float* x     = (const float*)d_in[0];
    const float* W_rbf = (const float*)d_in[1];
    const float* W_out = (const float*)d_in[2];
    const float* b_out = (const float*)d_in[3];
    float* out = (float*)d_out;

    rownorm_kernel<<<NDIM, 256>>>(x);
    conv_half_kernel<0><<<8192, 256>>>(x);
    conv_half_kernel<1><<<8192, 256>>>(W_out);
    transp_kernel<<<dim3(128, 128), dim3(32, 8)>>>(x);

    dim3 grid(NDIM / BN, NDIM / BM);   // 32 x 32
    hmma_gemm<0><<<grid, 256>>>(W_rbf, nullptr);
    hmma_gemm<1><<<grid, 256>>>(nullptr, nullptr);
    hmma_gemm<2><<<grid, 256>>>(b_out, out);
}

// round 5
// speedup vs baseline: 7.6786x; 1.0593x over previous
#include <cuda_runtime.h>
#include <cuda_fp16.h>
#include <cstdint>
#include <math.h>

#define NDIM 4096

// ---------------- device scratch (no allocs allowed) ------------------------
__device__ float  g_sq[NDIM];
__device__ __half g_xh    [(size_t)NDIM * NDIM];   // x  fp16 [B,F]
__device__ __half g_xth   [(size_t)NDIM * NDIM];   // x^T fp16 [F,B]
__device__ __half g_wouth [(size_t)NDIM * NDIM];   // W_out fp16 [OUT,F]
__device__ __half g_gramh [(size_t)NDIM * NDIM];   // gram fp16
__device__ __half g_mixedh[(size_t)NDIM * NDIM];   // mixed fp16

// ---------------- helpers ---------------------------------------------------
__device__ __forceinline__ uint32_t smem_u32(const void* p) {
    uint32_t a;
    asm("{ .reg .u64 t; cvta.to.shared.u64 t, %1; cvt.u32.u64 %0, t; }"
        : "=r"(a) : "l"(p));
    return a;
}
__device__ __forceinline__ void cp16(uint32_t dst, const void* src) {
    asm volatile("cp.async.cg.shared.global [%0], [%1], 16;"
                 :: "r"(dst), "l"(src) : "memory");
}
__device__ __forceinline__ void cp_commit() {
    asm volatile("cp.async.commit_group;" ::: "memory");
}
__device__ __forceinline__ void cp_wait2() {
    asm volatile("cp.async.wait_group 2;" ::: "memory");
}
__device__ __forceinline__ uint32_t swz128(uint32_t off) {
    return off ^ ((off >> 3) & 0x70);          // SW128, 128B rows
}
__device__ __forceinline__ void ldsm4(uint32_t& r0, uint32_t& r1,
                                      uint32_t& r2, uint32_t& r3, uint32_t a) {
    asm volatile("ldmatrix.sync.aligned.m8n8.x4.shared.b16 {%0,%1,%2,%3}, [%4];"
                 : "=r"(r0), "=r"(r1), "=r"(r2), "=r"(r3) : "r"(a));
}
__device__ __forceinline__ void mma16816(float* c, const uint32_t* a,
                                         const uint32_t* b) {
    asm volatile(
        "mma.sync.aligned.m16n8k16.row.col.f32.f16.f16.f32 "
        "{%0,%1,%2,%3}, {%4,%5,%6,%7}, {%8,%9}, {%0,%1,%2,%3};"
        : "+f"(c[0]), "+f"(c[1]), "+f"(c[2]), "+f"(c[3])
        : "r"(a[0]), "r"(a[1]), "r"(a[2]), "r"(a[3]), "r"(b[0]), "r"(b[1]));
}

// ---------------- GEMM config ----------------------------------------------
constexpr int BM = 128, BN = 256, BK = 64;     // BK halves = 128 B rows (SW128)
constexpr int NITER = NDIM / BK;               // 64
constexpr int A_BYTES = BM * BK * 2;           // 16384
constexpr int B_BYTES = BN * BK * 2;           // 32768
constexpr int STAGE_BYTES = A_BYTES + B_BYTES; // 49152
constexpr int NSTAGE = 4;
constexpr int SMEM_TOTAL = NSTAGE * STAGE_BYTES;   // 196608

// MODE 0: S = x x^T + dist/exp -> g_gramh
// MODE 1: mixed = gram @ x (B = x^T)   -> g_mixedh
// MODE 2: out = mixed @ W_out^T + b    -> Cext (fp32)
template <int MODE>
__global__ void __launch_bounds__(512)
hmma_gemm(const float* __restrict__ aux, float* __restrict__ Cext)
{
    extern __shared__ __align__(1024) char smem[];
    const uint32_t sb = smem_u32(smem);

    const int tid = threadIdx.x, wid = tid >> 5, lane = tid & 31;
    const int bm = blockIdx.y * BM, bn = blockIdx.x * BN;
    const int wm = (wid >> 3) * 64;      // 2 warps along M
    const int wn = (wid & 7) * 32;       // 8 warps along N

    const __half* Ag = (MODE == 0) ? g_xh : (MODE == 1) ? g_gramh : g_mixedh;
    const __half* Bg = (MODE == 0) ? g_xh : (MODE == 1) ? g_xth   : g_wouth;

    // cp.async mapping: A = 1024 16B chunks (2/thread), B = 2048 (4/thread)
    // chunk -> row = chunk>>3, colgroup = chunk&7 (16B = 8 halves)
    const int raA0 = (tid)        >> 3, caA0 = (tid)        & 7;
    const int raA1 = (tid + 512)  >> 3, caA1 = (tid + 512)  & 7;
    const __half* gA0 = Ag + (size_t)(bm + raA0) * NDIM + caA0 * 8;
    const __half* gA1 = Ag + (size_t)(bm + raA1) * NDIM + caA1 * 8;
    const uint32_t sA0 = swz128(raA0 * 128 + caA0 * 16);
    const uint32_t sA1 = swz128(raA1 * 128 + caA1 * 16);

    const __half* gB[4];
    uint32_t sB[4];
#pragma unroll
    for (int t = 0; t < 4; t++) {
        int ch = tid + t * 512;
        int r = ch >> 3, c = ch & 7;
        gB[t] = Bg + (size_t)(bn + r) * NDIM + c * 8;
        sB[t] = swz128(r * 128 + c * 16);
    }

    // ldmatrix lane offsets (bytes, pre-swizzle), 128B rows
    const uint32_t aRB = (uint32_t)(wm + (lane & 15)) * 128 + (lane >> 4) * 16;
    const uint32_t bRB = (uint32_t)(wn + (lane & 7) + ((lane >> 4) << 3)) * 128 +
                         ((lane >> 3) & 1) * 16;

    float acc[4][4][4];
#pragma unroll
    for (int i = 0; i < 4; i++)
#pragma unroll
        for (int j = 0; j < 4; j++)
#pragma unroll
            for (int q = 0; q < 4; q++) acc[i][j][q] = 0.f;

    // prologue: stages 0..2
#pragma unroll
    for (int t = 0; t < 3; t++) {
        const uint32_t base = sb + t * STAGE_BYTES;
        const int kt = t * BK;
        cp16(base + sA0, gA0 + kt);
        cp16(base + sA1, gA1 + kt);
#pragma unroll
        for (int q = 0; q < 4; q++)
            cp16(base + A_BYTES + sB[q], gB[q] + kt);
        cp_commit();
    }

    for (int it = 0; it < NITER; ++it) {
        cp_wait2();
        __syncthreads();

        const int nt = it + 3;
        if (nt < NITER) {
            const uint32_t base = sb + (nt & 3) * STAGE_BYTES;
            const int kt = nt * BK;
            cp16(base + sA0, gA0 + kt);
            cp16(base + sA1, gA1 + kt);
#pragma unroll
            for (int q = 0; q < 4; q++)
                cp16(base + A_BYTES + sB[q], gB[q] + kt);
        }
        cp_commit();

        const uint32_t abase = sb + (it & 3) * STAGE_BYTES;
        const uint32_t bbase = abase + A_BYTES;

#pragma unroll
        for (int ks = 0; ks < 4; ks++) {
            uint32_t af[4][4], bf[4][2];
#pragma unroll
            for (int mf = 0; mf < 4; mf++)
                ldsm4(af[mf][0], af[mf][1], af[mf][2], af[mf][3],
                      abase + swz128(aRB + mf * 2048 + ks * 32));
#pragma unroll
            for (int nf2 = 0; nf2 < 2; nf2++) {
                uint32_t r0, r1, r2, r3;
                // B stored [N,K]: non-trans ldmatrix = correct mma B fragment
                ldsm4(r0, r1, r2, r3,
                      bbase + swz128(bRB + nf2 * 2048 + ks * 32));
                bf[2 * nf2][0] = r0; bf[2 * nf2][1] = r1;
                bf[2 * nf2 + 1][0] = r2; bf[2 * nf2 + 1][1] = r3;
            }
#pragma unroll
            for (int mf = 0; mf < 4; mf++)
#pragma unroll
                for (int nf = 0; nf < 4; nf++)
                    mma16816(acc[mf][nf], af[mf], bf[nf]);
        }
    }

    // ---------------- epilogue (register accumulators) ----------------------
    const int rb = bm + wm + (lane >> 2);
    const int cb = bn + wn + (lane & 3) * 2;

    if (MODE == 0) {
        float2 sqc[4];
#pragma unroll
        for (int nf = 0; nf < 4; nf++)
            sqc[nf] = *reinterpret_cast<const float2*>(&g_sq[cb + nf * 8]);
#pragma unroll
        for (int mf = 0; mf < 4; mf++)
#pragma unroll
            for (int rs = 0; rs < 2; rs++) {
                const int row = rb + mf * 16 + rs * 8;
                const float sqi = g_sq[row];
                const float* wr = aux + (size_t)row * NDIM;
                __half* orow = g_gramh + (size_t)row * NDIM;
#pragma unroll
                for (int nf = 0; nf < 4; nf++) {
                    const int col = cb + nf * 8;
                    float2 w2 = *reinterpret_cast<const float2*>(&wr[col]);
                    float s0 = acc[mf][nf][rs * 2 + 0];
                    float s1 = acc[mf][nf][rs * 2 + 1];
                    float d0 = sqrtf(fmaxf(sqi + sqc[nf].x - 2.f * s0, 0.f));
                    float d1 = sqrtf(fmaxf(sqi + sqc[nf].y - 2.f * s1, 0.f));
                    __half2 h = __floats2half2_rn(__expf(-fabsf(w2.x) * d0),
                                                  __expf(-fabsf(w2.y) * d1));
                    *reinterpret_cast<__half2*>(&orow[col]) = h;
                }
            }
    } else if (MODE == 1) {
#pragma unroll
        for (int mf = 0; mf < 4; mf++)
#pragma unroll
            for (int rs = 0; rs < 2; rs++) {
                const int row = rb + mf * 16 + rs * 8;
                __half* orow = g_mixedh + (size_t)row * NDIM;
#pragma unroll
                for (int nf = 0; nf < 4; nf++) {
                    __half2 h = __floats2half2_rn(acc[mf][nf][rs * 2 + 0],
                                                  acc[mf][nf][rs * 2 + 1]);
                    *reinterpret_cast<__half2*>(&orow[cb + nf * 8]) = h;
                }
            }
    } else {
        float2 bias2[4];
#pragma unroll
        for (int nf = 0; nf < 4; nf++)
            bias2[nf] = *reinterpret_cast<const float2*>(&aux[cb + nf * 8]);
#pragma unroll
        for (int mf = 0; mf < 4; mf++)
#pragma unroll
            for (int rs = 0; rs < 2; rs++) {
                const int row = rb + mf * 16 + rs * 8;
                float* orow = Cext + (size_t)row * NDIM;
#pragma unroll
                for (int nf = 0; nf < 4; nf++) {
                    float2 v;
                    v.x = acc[mf][nf][rs * 2 + 0] + bias2[nf].x;
                    v.y = acc[mf][nf][rs * 2 + 1] + bias2[nf].y;
                    *reinterpret_cast<float2*>(&orow[cb + nf * 8]) = v;
                }
            }
    }
}

// ---------------- prep kernels ---------------------------------------------
__global__ void rownorm_kernel(const float* __restrict__ x) {
    const int row = blockIdx.x;
    const float4* xr = reinterpret_cast<const float4*>(x + (size_t)row * NDIM);
    float s = 0.f;
    for (int i = threadIdx.x; i < NDIM / 4; i += blockDim.x) {
        float4 v = xr[i];
        s += v.x * v.x + v.y * v.y + v.z * v.z + v.w * v.w;
    }
    __shared__ float red[256];
    red[threadIdx.x] = s;
    __syncthreads();
    for (int off = 128; off > 0; off >>= 1) {
        if (threadIdx.x < off) red[threadIdx.x] += red[threadIdx.x + off];
        __syncthreads();
    }
    if (threadIdx.x == 0) g_sq[row] = red[0];
}

// fused: x -> g_xh (fp16) and g_xth (fp16 transpose), one read of x
__global__ void prep_x_kernel(const float* __restrict__ src) {
    __shared__ float t[32][33];
    const int bx = blockIdx.x * 32, by = blockIdx.y * 32;
    const int tx = threadIdx.x, ty = threadIdx.y;   // (32, 8)
#pragma unroll
    for (int j = 0; j < 32; j += 8) {
        float v = src[(size_t)(by + ty + j) * NDIM + bx + tx];
        t[ty + j][tx] = v;
        g_xh[(size_t)(by + ty + j) * NDIM + bx + tx] = __float2half(v);
    }
    __syncthreads();
#pragma unroll
    for (int j = 0; j < 32; j += 8)
        g_xth[(size_t)(bx + ty + j) * NDIM + by + tx] = __float2half(t[tx][ty + j]);
}

__global__ void conv_wout_kernel(const float* __restrict__ src) {
    size_t i = ((size_t)blockIdx.x * blockDim.x + threadIdx.x) * 8;
    const float4* s = reinterpret_cast<const float4*>(src + i);
    float4 a = s[0], b = s[1];
    __half2 h0 = __floats2half2_rn(a.x, a.y);
    __half2 h1 = __floats2half2_rn(a.z, a.w);
    __half2 h2 = __floats2half2_rn(b.x, b.y);
    __half2 h3 = __floats2half2_rn(b.z, b.w);
    uint4 o;
    o.x = *reinterpret_cast<uint32_t*>(&h0);
    o.y = *reinterpret_cast<uint32_t*>(&h1);
    o.z = *reinterpret_cast<uint32_t*>(&h2);
    o.w = *reinterpret_cast<uint32_t*>(&h3);
    *reinterpret_cast<uint4*>(g_wouth + i) = o;
}

// ---------------------------------------------------------------------------
extern "C" void kernel_launch(void* const* d_in, const int* in_sizes, int n_in,
                              void* d_out, int out_size)
{
    const float* x     = (const float*)d_in[0];
    const float* W_rbf = (const float*)d_in[1];
    const float* W_out = (const float*)d_in[2];
    const float* b_out = (const float*)d_in[3];
    float* out = (float*)d_out;

    static bool attr_done = false;
    if (!attr_done) {
        cudaFuncSetAttribute(hmma_gemm<0>, cudaFuncAttributeMaxDynamicSharedMemorySize, SMEM_TOTAL);
        cudaFuncSetAttribute(hmma_gemm<1>, cudaFuncAttributeMaxDynamicSharedMemorySize, SMEM_TOTAL);
        cudaFuncSetAttribute(hmma_gemm<2>, cudaFuncAttributeMaxDynamicSharedMemorySize, SMEM_TOTAL);
        attr_done = true;
    }

    rownorm_kernel<<<NDIM, 256>>>(x);
    prep_x_kernel<<<dim3(128, 128), dim3(32, 8)>>>(x);
    conv_wout_kernel<<<8192, 256>>>(W_out);

    dim3 grid(NDIM / BN, NDIM / BM);   // 16 x 32
    hmma_gemm<0><<<grid, 512, SMEM_TOTAL>>>(W_rbf, nullptr);
    hmma_gemm<1><<<grid, 512, SMEM_TOTAL>>>(nullptr, nullptr);
    hmma_gemm<2><<<grid, 512, SMEM_TOTAL>>>(b_out, out);
}